// round 2
// baseline (speedup 1.0000x reference)
#include <cuda_runtime.h>

#define Bv 64
#define Kv 8
#define HWv 16384
#define HW4 4096
#define EPSF 1e-15f
#define CHUNKS 8
#define NBLK1 (Bv * CHUNKS)

// scratch (no allocations allowed -> device globals)
__device__ float g_partial[NBLK1 * 72];  // per (b,chunk): 64 cross + 8 ent sums
__device__ int   g_inv[Bv * Kv];         // col -> source pred row
__device__ float g_cost[Bv];             // per-batch min assignment cost

// ---------------------------------------------------------------------------
// Kernel 1: per (batch, hw-chunk) partial sums of
//   cross[i][j] = sum_hw t_j * log(p_i + eps)   (64 values)
//   entraw[j]   = sum_hw t_j * log(t_j + eps)   (8 values)
// Grid: 512 blocks x 256 threads, each thread 2 float4 groups (8 positions).
// ---------------------------------------------------------------------------
__global__ __launch_bounds__(256) void k1(const float4* __restrict__ pred4,
                                          const float4* __restrict__ aug4) {
    const int bx = blockIdx.x;
    const int b = bx >> 3, chunk = bx & 7;
    const int tid = threadIdx.x;

    float acc[72];
#pragma unroll
    for (int v = 0; v < 72; v++) acc[v] = 0.f;

    const float4* pb = pred4 + (size_t)b * Kv * HW4;
    const float4* tb = aug4  + (size_t)b * Kv * HW4;

#pragma unroll
    for (int gset = 0; gset < 2; gset++) {
        const int idx = chunk * 512 + gset * 256 + tid;
        float lpv[4][8];
#pragma unroll
        for (int i = 0; i < 8; i++) {
            float4 pv = pb[i * HW4 + idx];
            lpv[0][i] = __logf(pv.x + EPSF);
            lpv[1][i] = __logf(pv.y + EPSF);
            lpv[2][i] = __logf(pv.z + EPSF);
            lpv[3][i] = __logf(pv.w + EPSF);
        }
#pragma unroll
        for (int j = 0; j < 8; j++) {
            float4 tv4 = tb[j * HW4 + idx];
            float tc[4] = {tv4.x, tv4.y, tv4.z, tv4.w};
#pragma unroll
            for (int c = 0; c < 4; c++) {
                float tv = tc[c];
                acc[64 + j] += tv * __logf(tv + EPSF);
#pragma unroll
                for (int i = 0; i < 8; i++)
                    acc[i * 8 + j] += tv * lpv[c][i];
            }
        }
    }

    // deterministic block reduction: warp shuffle then 8-warp smem sum
    __shared__ float sm[8][72];
    const int lane = tid & 31, warp = tid >> 5;
#pragma unroll
    for (int v = 0; v < 72; v++) {
        float s = acc[v];
#pragma unroll
        for (int o = 16; o > 0; o >>= 1) s += __shfl_xor_sync(0xffffffffu, s, o);
        if (lane == 0) sm[warp][v] = s;
    }
    __syncthreads();
    if (tid < 72) {
        float s = 0.f;
#pragma unroll
        for (int w = 0; w < 8; w++) s += sm[w][tid];
        g_partial[bx * 72 + tid] = s;
    }
}

// ---------------------------------------------------------------------------
// Kernel 2: per batch — finish C[i][j] = ent[j] - cross[i][j], exact
// assignment via suffix bitmask DP, forward greedy backtrack (smallest j on
// ties == lexicographically-first permutation, matching itertools argmin).
// Grid: 64 blocks x 128 threads.
// ---------------------------------------------------------------------------
__global__ __launch_bounds__(128) void k2() {
    const int b = blockIdx.x, t = threadIdx.x;
    __shared__ float raw[72];
    __shared__ float C[8][8];
    __shared__ float g[256];

    if (t < 72) {
        float s = 0.f;
#pragma unroll
        for (int c = 0; c < 8; c++) s += g_partial[(b * 8 + c) * 72 + t];
        raw[t] = s * (1.0f / (float)HWv);
    }
    __syncthreads();
    if (t < 64) C[t >> 3][t & 7] = raw[64 + (t & 7)] - raw[t];
    if (t == 0) g[0] = 0.f;
    __syncthreads();

    // g[mask] = min cost assigning rows (8-popc(mask) .. 7) to columns in mask
    for (int c = 1; c <= 8; c++) {
        const int row = 8 - c;
        for (int m = t; m < 256; m += 128) {
            if (__popc(m) == c) {
                float best = 3.4e38f;
#pragma unroll
                for (int j = 0; j < 8; j++)
                    if (m & (1 << j)) {
                        float v = g[m ^ (1 << j)] + C[row][j];
                        best = fminf(best, v);
                    }
                g[m] = best;
            }
        }
        __syncthreads();
    }

    if (t == 0) {
        g_cost[b] = g[255];
        int mask = 255;
        for (int r = 0; r < 8; r++) {
            float best = 3.4e38f;
            int bj = 0;
#pragma unroll
            for (int j = 0; j < 8; j++)
                if (mask & (1 << j)) {
                    float v = C[r][j] + g[mask ^ (1 << j)];
                    if (v < best) { best = v; bj = j; }
                }
            // row r assigned to column bj  =>  output column bj sources row r
            g_inv[b * 8 + bj] = r;
            mask ^= (1 << bj);
        }
    }
}

// ---------------------------------------------------------------------------
// Kernel 3: out[0] = mean loss; out[1..] = permuted pred copy.
// ---------------------------------------------------------------------------
__global__ __launch_bounds__(256) void k3(const float* __restrict__ pred,
                                          float* __restrict__ out) {
    const int idx = blockIdx.x * 256 + threadIdx.x;
    if (idx == 0) {
        float s = 0.f;
        for (int b = 0; b < Bv; b++) s += g_cost[b];  // fixed order: deterministic
        out[0] = s / (float)(Bv * Kv);
    }
    if (idx < Bv * Kv * HWv) {
        const int plane = idx >> 14;          // b*8 + i
        const int pos = idx & (HWv - 1);
        const int bbase = plane & ~7;         // b*8
        const int r = g_inv[plane];
        out[1 + idx] = pred[(size_t)(bbase + r) * HWv + pos];
    }
}

extern "C" void kernel_launch(void* const* d_in, const int* in_sizes, int n_in,
                              void* d_out, int out_size) {
    const float* pred = (const float*)d_in[0];
    const float* aug  = (const float*)d_in[1];
    float* out = (float*)d_out;

    k1<<<NBLK1, 256>>>((const float4*)pred, (const float4*)aug);
    k2<<<Bv, 128>>>();
    k3<<<(Bv * Kv * HWv + 255) / 256, 256>>>(pred, out);
}

// round 3
// speedup vs baseline: 1.1340x; 1.1340x over previous
#include <cuda_runtime.h>

#define Bv 64
#define Kv 8
#define HWv 16384
#define HW4 4096
#define EPSF 1e-15f
#define CHUNKS 8
#define NBLK1 (Bv * CHUNKS)
#define TOT4 2097152   // (B*K*HW)/4

// scratch (no allocations allowed -> device globals)
__device__ float g_partial[NBLK1 * 72];  // per (b,chunk): 64 cross + 8 ent sums
__device__ int   g_inv[Bv * Kv];         // col -> source pred row
__device__ float g_cost[Bv];             // per-batch min assignment cost

// ---------------------------------------------------------------------------
// Kernel 1: per (batch, hw-chunk) partial sums of
//   cross[i][j] = sum_hw t_j * log(p_i + eps)
//   entraw[j]   = sum_hw t_j * log(t_j + eps)
// i-dimension split across two 128-thread groups -> 36 accumulators/thread,
// 3 CTAs/SM. Each thread covers 4 float4 positions (s-strided).
// ---------------------------------------------------------------------------
__global__ __launch_bounds__(256, 3) void k1(const float4* __restrict__ pred4,
                                             const float4* __restrict__ aug4) {
    const int bx = blockIdx.x;
    const int b = bx >> 3, chunk = bx & 7;
    const int tid = threadIdx.x;
    const int igrp = tid >> 7;       // which half of the i-range (warp-uniform)
    const int lt = tid & 127;

    float acc[32];                   // [ii][j], ii = local i (4 rows)
    float ent[4];                    // this group's 4 j's
#pragma unroll
    for (int v = 0; v < 32; v++) acc[v] = 0.f;
#pragma unroll
    for (int v = 0; v < 4; v++) ent[v] = 0.f;

    const float4* pb = pred4 + (size_t)b * Kv * HW4 + (size_t)(igrp << 2) * HW4;
    const float4* tb = aug4  + (size_t)b * Kv * HW4;

#pragma unroll
    for (int s = 0; s < 4; s++) {
        const int idx = chunk * 512 + s * 128 + lt;

        float lp[4][4];
#pragma unroll
        for (int ii = 0; ii < 4; ii++) {
            float4 pv = pb[ii * HW4 + idx];
            lp[0][ii] = __logf(pv.x + EPSF);
            lp[1][ii] = __logf(pv.y + EPSF);
            lp[2][ii] = __logf(pv.z + EPSF);
            lp[3][ii] = __logf(pv.w + EPSF);
        }

        float4 tnext = tb[idx];
#pragma unroll
        for (int j = 0; j < 8; j++) {
            float4 tv = tnext;
            if (j < 7) tnext = tb[(j + 1) * HW4 + idx];
            float tc[4] = {tv.x, tv.y, tv.z, tv.w};
#pragma unroll
            for (int c = 0; c < 4; c++) {
                const float t = tc[c];
#pragma unroll
                for (int ii = 0; ii < 4; ii++)
                    acc[ii * 8 + j] += t * lp[c][ii];
            }
            if ((j >> 2) == igrp) {          // warp-uniform branch
                const int jj = j & 3;
#pragma unroll
                for (int c = 0; c < 4; c++)
                    ent[jj] += tc[c] * __logf(tc[c] + EPSF);
            }
        }
    }

    // deterministic reduction: warp shuffle -> smem -> 72-thread assembly
    __shared__ float sm[8][36];
    const int lane = tid & 31, warp = tid >> 5;
#pragma unroll
    for (int v = 0; v < 36; v++) {
        float sv = (v < 32) ? acc[v] : ent[v - 32];
#pragma unroll
        for (int o = 16; o > 0; o >>= 1) sv += __shfl_xor_sync(0xffffffffu, sv, o);
        if (lane == 0) sm[warp][v] = sv;
    }
    __syncthreads();
    if (tid < 72) {
        float ssum = 0.f;
        if (tid < 64) {
            const int i = tid >> 3, j = tid & 7;
            const int wb = (i >> 2) * 4, li = i & 3;
#pragma unroll
            for (int w = 0; w < 4; w++) ssum += sm[wb + w][li * 8 + j];
        } else {
            const int j = tid - 64;
            const int wb = (j >> 2) * 4;
#pragma unroll
            for (int w = 0; w < 4; w++) ssum += sm[wb + w][32 + (j & 3)];
        }
        g_partial[bx * 72 + tid] = ssum;
    }
}

// ---------------------------------------------------------------------------
// Kernel 2: per batch — C[i][j] = ent[j] - cross[i][j]; exact assignment via
// suffix bitmask DP; forward greedy backtrack (smallest j on ties ==
// lexicographically-first permutation, matching itertools argmin).
// ---------------------------------------------------------------------------
__global__ __launch_bounds__(128) void k2() {
    const int b = blockIdx.x, t = threadIdx.x;
    __shared__ float raw[72];
    __shared__ float C[8][8];
    __shared__ float g[256];

    if (t < 72) {
        float s = 0.f;
#pragma unroll
        for (int c = 0; c < 8; c++) s += g_partial[(b * 8 + c) * 72 + t];
        raw[t] = s * (1.0f / (float)HWv);
    }
    __syncthreads();
    if (t < 64) C[t >> 3][t & 7] = raw[64 + (t & 7)] - raw[t];
    if (t == 0) g[0] = 0.f;
    __syncthreads();

    for (int c = 1; c <= 8; c++) {
        const int row = 8 - c;
        for (int m = t; m < 256; m += 128) {
            if (__popc(m) == c) {
                float best = 3.4e38f;
#pragma unroll
                for (int j = 0; j < 8; j++)
                    if (m & (1 << j)) {
                        float v = g[m ^ (1 << j)] + C[row][j];
                        best = fminf(best, v);
                    }
                g[m] = best;
            }
        }
        __syncthreads();
    }

    if (t == 0) {
        g_cost[b] = g[255];
        int mask = 255;
        for (int r = 0; r < 8; r++) {
            float best = 3.4e38f;
            int bj = 0;
#pragma unroll
            for (int j = 0; j < 8; j++)
                if (mask & (1 << j)) {
                    float v = C[r][j] + g[mask ^ (1 << j)];
                    if (v < best) { best = v; bj = j; }
                }
            g_inv[b * 8 + bj] = r;   // output col bj sources pred row r
            mask ^= (1 << bj);
        }
    }
}

// ---------------------------------------------------------------------------
// Kernel 3: vectorized permuted copy with +1 realignment via shfl.
// out4[m] = (flat[4m-1], flat[4m], flat[4m+1], flat[4m+2]),  flat[-1] = loss.
// Blocks 0..8191 are full (TOT4 = 8192*256); block 8192 writes the tail scalar.
// ---------------------------------------------------------------------------
__global__ __launch_bounds__(256) void k3(const float* __restrict__ pred,
                                          float* __restrict__ out) {
    if (blockIdx.x == TOT4 / 256) {
        if (threadIdx.x == 0) {
            const int u = Bv * Kv * HWv - 1;
            const int pl = u >> 14, pos = u & (HWv - 1);
            const int sr = (pl & ~7) + g_inv[pl];
            out[Bv * Kv * HWv] = pred[(size_t)sr * HWv + pos];
        }
        return;
    }
    const int mi = blockIdx.x * 256 + threadIdx.x;   // [0, TOT4)
    const int pm = mi >> 12;                         // plane = (4m)>>14
    const int q = mi & (HW4 - 1);
    const int src = (pm & ~7) + g_inv[pm];

    const float4* pred4 = (const float4*)pred;
    float4 v = pred4[(size_t)src * HW4 + q];

    float prev = __shfl_up_sync(0xffffffffu, v.w, 1);
    if ((threadIdx.x & 31) == 0) {
        if (mi == 0) {
            float ssum = 0.f;
#pragma unroll
            for (int bb = 0; bb < Bv; bb++) ssum += g_cost[bb];  // fixed order
            prev = ssum * (1.0f / (float)(Bv * Kv));
        } else {
            const int u = 4 * mi - 1;
            const int pl = u >> 14, pos = u & (HWv - 1);
            const int sr = (pl & ~7) + g_inv[pl];
            prev = pred[(size_t)sr * HWv + pos];
        }
    }
    float4 o4;
    o4.x = prev; o4.y = v.x; o4.z = v.y; o4.w = v.z;
    ((float4*)out)[mi] = o4;
}

extern "C" void kernel_launch(void* const* d_in, const int* in_sizes, int n_in,
                              void* d_out, int out_size) {
    const float* pred = (const float*)d_in[0];
    const float* aug  = (const float*)d_in[1];
    float* out = (float*)d_out;

    k1<<<NBLK1, 256>>>((const float4*)pred, (const float4*)aug);
    k2<<<Bv, 128>>>();
    k3<<<TOT4 / 256 + 1, 256>>>(pred, out);
}

// round 5
// speedup vs baseline: 1.3131x; 1.1579x over previous
#include <cuda_runtime.h>
#include <cstdint>

#define Bv 64
#define Kv 8
#define HWv 16384
#define HW4 4096
#define EPSF 1e-15f
#define CHUNKS 16
#define NBLK1 (Bv * CHUNKS)     // 1024
#define TOT4 2097152            // (B*K*HW)/4

// scratch (no allocations allowed -> device globals)
__device__ float g_partial[NBLK1 * 72];  // per (b,chunk): 64 cross + 8 ent sums
__device__ int   g_inv[Bv * Kv];         // col -> source pred row
__device__ float g_cost[Bv];             // per-batch min assignment cost

__device__ __forceinline__ void cpa16(unsigned int dst, const void* src) {
    asm volatile("cp.async.cg.shared.global [%0], [%1], 16;\n" :: "r"(dst), "l"(src));
}
__device__ __forceinline__ void cpcommit() {
    asm volatile("cp.async.commit_group;\n");
}
template <int N> __device__ __forceinline__ void cpwait() {
    asm volatile("cp.async.wait_group %0;\n" :: "n"(N));
}

// ---------------------------------------------------------------------------
// Kernel 1: smem-tiled micro-GEMM.
//   cross[i][j] = sum_hw t_j * log(p_i + eps)   ent[j] = sum_hw t_j*log(t_j+eps)
// Block (b, chunk of 256 f4 per row). 4 stages of 64 f4, cp.async double-buffer.
// Compute: thread owns 4x4 (i,j) tile, 1 f4 of hw per stage.
// ---------------------------------------------------------------------------
__global__ __launch_bounds__(256, 3) void k1(const float4* __restrict__ pred4,
                                             const float4* __restrict__ aug4) {
    __shared__ float4 sp[2][8][64];   // raw pred tiles
    __shared__ float4 stt[2][8][64];  // raw aug tiles
    __shared__ float red[8][16];
    __shared__ float entw[4][4];

    const int bx = blockIdx.x;
    const int b = bx >> 4, chunk = bx & 15;
    const int tid = threadIdx.x;
    const int row = tid >> 5, lane = tid & 31;

    const float4* pb = pred4 + (size_t)b * (Kv * HW4) + (size_t)row * HW4 + chunk * 256 + lane;
    const float4* tb = aug4  + (size_t)b * (Kv * HW4) + (size_t)row * HW4 + chunk * 256 + lane;

    const unsigned int dp0 = (unsigned int)__cvta_generic_to_shared(&sp[0][row][lane]);
    const unsigned int dt0 = (unsigned int)__cvta_generic_to_shared(&stt[0][row][lane]);
    const unsigned int bufstride = (unsigned int)((char*)&sp[1][0][0] - (char*)&sp[0][0][0]);

    // compute-phase mapping
    const int g = tid >> 6;           // warp-uniform
    const int it = g >> 1, jt = g & 1;
    const int hwq = tid & 63;

    float acc[4][4];
#pragma unroll
    for (int r = 0; r < 4; r++)
#pragma unroll
        for (int c = 0; c < 4; c++) acc[r][c] = 0.f;
    float entacc[4] = {0.f, 0.f, 0.f, 0.f};

    // stage 0 issue
    {
        cpa16(dp0, pb);            cpa16(dp0 + 32 * 16, pb + 32);
        cpa16(dt0, tb);            cpa16(dt0 + 32 * 16, tb + 32);
        cpcommit();
    }

#pragma unroll
    for (int s = 0; s < 4; s++) {
        if (s + 1 < 4) {
            const unsigned int off = ((s + 1) & 1) * bufstride;
            const float4* ps = pb + (s + 1) * 64;
            const float4* ts = tb + (s + 1) * 64;
            cpa16(dp0 + off, ps);            cpa16(dp0 + off + 32 * 16, ps + 32);
            cpa16(dt0 + off, ts);            cpa16(dt0 + off + 32 * 16, ts + 32);
            cpcommit();
            cpwait<1>();
        } else {
            cpwait<0>();
        }
        __syncthreads();

        const int buf = s & 1;
        float4 a[4], bb[4];
#pragma unroll
        for (int r = 0; r < 4; r++) a[r] = sp[buf][4 * it + r][hwq];
#pragma unroll
        for (int c = 0; c < 4; c++) bb[c] = stt[buf][4 * jt + c][hwq];

        // logs in place on p
#pragma unroll
        for (int r = 0; r < 4; r++) {
            a[r].x = __logf(a[r].x + EPSF);
            a[r].y = __logf(a[r].y + EPSF);
            a[r].z = __logf(a[r].z + EPSF);
            a[r].w = __logf(a[r].w + EPSF);
        }
        // entropy: only it==0 threads, each t element covered exactly once
        if (it == 0) {
#pragma unroll
            for (int c = 0; c < 4; c++) {
                entacc[c] += bb[c].x * __logf(bb[c].x + EPSF)
                           + bb[c].y * __logf(bb[c].y + EPSF)
                           + bb[c].z * __logf(bb[c].z + EPSF)
                           + bb[c].w * __logf(bb[c].w + EPSF);
            }
        }
#pragma unroll
        for (int r = 0; r < 4; r++)
#pragma unroll
            for (int c = 0; c < 4; c++)
                acc[r][c] += bb[c].x * a[r].x + bb[c].y * a[r].y
                           + bb[c].z * a[r].z + bb[c].w * a[r].w;
        __syncthreads();
    }

    // ---- deterministic reductions ----
    const int warp = tid >> 5, wl = tid & 31;
#pragma unroll
    for (int r = 0; r < 4; r++)
#pragma unroll
        for (int c = 0; c < 4; c++) {
            float v = acc[r][c];
#pragma unroll
            for (int o = 16; o > 0; o >>= 1) v += __shfl_xor_sync(0xffffffffu, v, o);
            if (wl == 0) red[warp][r * 4 + c] = v;
        }
    if (warp < 4) {
#pragma unroll
        for (int c = 0; c < 4; c++) {
            float v = entacc[c];
#pragma unroll
            for (int o = 16; o > 0; o >>= 1) v += __shfl_xor_sync(0xffffffffu, v, o);
            if (wl == 0) entw[warp][c] = v;
        }
    }
    __syncthreads();

    if (tid < 64) {
        const int i = tid >> 3, j = tid & 7;
        const int gg = (i >> 2) * 2 + (j >> 2);
        const int k = (i & 3) * 4 + (j & 3);
        g_partial[bx * 72 + tid] = red[2 * gg][k] + red[2 * gg + 1][k];
    } else if (tid < 72) {
        const int j = tid - 64;
        g_partial[bx * 72 + tid] = entw[2 * (j >> 2)][j & 3] + entw[2 * (j >> 2) + 1][j & 3];
    }
}

// ---------------------------------------------------------------------------
// Kernel 2: per batch — C[i][j] = ent[j] - cross[i][j]; exact assignment via
// suffix bitmask DP; forward greedy backtrack (smallest j on ties ==
// lexicographically-first permutation, matching itertools argmin).
// ---------------------------------------------------------------------------
__global__ __launch_bounds__(128) void k2() {
    const int b = blockIdx.x, t = threadIdx.x;
    __shared__ float raw[72];
    __shared__ float C[8][8];
    __shared__ float g[256];

    if (t < 72) {
        float s = 0.f;
#pragma unroll
        for (int c = 0; c < CHUNKS; c++) s += g_partial[(b * CHUNKS + c) * 72 + t];
        raw[t] = s * (1.0f / (float)HWv);
    }
    __syncthreads();
    if (t < 64) C[t >> 3][t & 7] = raw[64 + (t & 7)] - raw[t];
    if (t == 0) g[0] = 0.f;
    __syncthreads();

    for (int c = 1; c <= 8; c++) {
        const int rowi = 8 - c;
        for (int m = t; m < 256; m += 128) {
            if (__popc(m) == c) {
                float best = 3.4e38f;
#pragma unroll
                for (int j = 0; j < 8; j++)
                    if (m & (1 << j)) {
                        float v = g[m ^ (1 << j)] + C[rowi][j];
                        best = fminf(best, v);
                    }
                g[m] = best;
            }
        }
        __syncthreads();
    }

    if (t == 0) {
        g_cost[b] = g[255];
        int mask = 255;
        for (int r = 0; r < 8; r++) {
            float best = 3.4e38f;
            int bj = 0;
#pragma unroll
            for (int j = 0; j < 8; j++)
                if (mask & (1 << j)) {
                    float v = C[r][j] + g[mask ^ (1 << j)];
                    if (v < best) { best = v; bj = j; }
                }
            g_inv[b * 8 + bj] = r;   // output col bj sources pred row r
            mask ^= (1 << bj);
        }
    }
}

// ---------------------------------------------------------------------------
// Kernel 3: vectorized permuted copy with +1 realignment via shfl.
// out4[m] = (flat[4m-1], flat[4m], flat[4m+1], flat[4m+2]),  flat[-1] = loss.
// ---------------------------------------------------------------------------
__global__ __launch_bounds__(256) void k3(const float* __restrict__ pred,
                                          float* __restrict__ out) {
    if (blockIdx.x == TOT4 / 256) {
        if (threadIdx.x == 0) {
            const int u = Bv * Kv * HWv - 1;
            const int pl = u >> 14, pos = u & (HWv - 1);
            const int sr = (pl & ~7) + g_inv[pl];
            out[Bv * Kv * HWv] = pred[(size_t)sr * HWv + pos];
        }
        return;
    }
    const int mi = blockIdx.x * 256 + threadIdx.x;   // [0, TOT4)
    const int pm = mi >> 12;                         // plane = (4m)>>14
    const int q = mi & (HW4 - 1);
    const int src = (pm & ~7) + g_inv[pm];

    const float4* pred4 = (const float4*)pred;
    float4 v = pred4[(size_t)src * HW4 + q];

    float prev = __shfl_up_sync(0xffffffffu, v.w, 1);
    if ((threadIdx.x & 31) == 0) {
        if (mi == 0) {
            float ssum = 0.f;
#pragma unroll
            for (int bb = 0; bb < Bv; bb++) ssum += g_cost[bb];  // fixed order
            prev = ssum * (1.0f / (float)(Bv * Kv));
        } else {
            const int u = 4 * mi - 1;
            const int pl = u >> 14, pos = u & (HWv - 1);
            const int sr = (pl & ~7) + g_inv[pl];
            prev = pred[(size_t)sr * HWv + pos];
        }
    }
    float4 o4;
    o4.x = prev; o4.y = v.x; o4.z = v.y; o4.w = v.z;
    ((float4*)out)[mi] = o4;
}

extern "C" void kernel_launch(void* const* d_in, const int* in_sizes, int n_in,
                              void* d_out, int out_size) {
    const float* pred = (const float*)d_in[0];
    const float* aug  = (const float*)d_in[1];
    float* out = (float*)d_out;

    k1<<<NBLK1, 256>>>((const float4*)pred, (const float4*)aug);
    k2<<<Bv, 128>>>();
    k3<<<TOT4 / 256 + 1, 256>>>(pred, out);
}